// round 2
// baseline (speedup 1.0000x reference)
#include <cuda_runtime.h>
#include <math.h>

#define BATCH 131072
#define SN 32
#define H1 10
#define H2 6
#define NBLK 1024
#define ROWS_PER_BLK (BATCH / NBLK)   // 128
#define TY 8
#define RPT 2                          // rows per thread per iteration
#define NPARAM 103                     // w1(10) b1(10) w1s2(10) W2(60) b2(6) w3(6) b3(1)

// ---- static scratch (no allocations allowed) ----
__device__ float  g_partial[NBLK * 96];   // [block][stat(3)][subnet(32)]
__device__ double g_sums[96];
__device__ float  g_mean[SN];
__device__ float  g_rstd[SN];

// accurate-enough fast tanh: (e^{2x}-1)/(e^{2x}+1) via MUFU.EX2 + MUFU.RCP
// abs error ~1e-7 near 0/1; negative underflow -> exactly -1; clamp pos overflow.
__device__ __forceinline__ float ftanh(float x) {
    float a = fminf(x * 2.8853900817779268f, 126.0f);  // 2*log2(e)
    float e;
    asm("ex2.approx.f32 %0, %1;" : "=f"(e) : "f"(a));
    float r;
    asm("rcp.approx.f32 %0, %1;" : "=f"(r) : "f"(e + 1.0f));
    return (e - 1.0f) * r;
}

__global__ void __launch_bounds__(256, 2) k_forward(
    const float* __restrict__ x,
    const float* __restrict__ W1, const float* __restrict__ b1,
    const float* __restrict__ W2, const float* __restrict__ b2,
    const float* __restrict__ W3, const float* __restrict__ b3,
    float* __restrict__ out)
{
    __shared__ float sp[NPARAM * 32];        // [param][subnet] -> bank = subnet
    __shared__ float red[3][TY][32];

    const int tx = threadIdx.x;              // subnet
    const int ty = threadIdx.y;
    const int tid = ty * 32 + tx;

    // cooperative param load + precompute -2*w1^2
    for (int p = tid; p < NPARAM * 32; p += 256) {
        int param = p >> 5, s = p & 31;
        float v;
        if      (param < 10)  v = W1[s * 10 + param];
        else if (param < 20)  v = b1[s * 10 + (param - 10)];
        else if (param < 30)  { float w = W1[s * 10 + (param - 20)]; v = -2.0f * w * w; }
        else if (param < 90)  v = W2[s * 60 + (param - 30)];          // i*6+k
        else if (param < 96)  v = b2[s * 6 + (param - 90)];
        else if (param < 102) v = W3[s * 6 + (param - 96)];
        else                  v = b3[s];
        sp[p] = v;
    }
    __syncthreads();

    const float* spx = sp + tx;              // per-thread param base (stride 32)
    float acc_o = 0.0f, acc_o2 = 0.0f, acc_g = 0.0f;
    const int row0 = blockIdx.x * ROWS_PER_BLK;

    #pragma unroll 1
    for (int it = 0; it < ROWS_PER_BLK / (TY * RPT); ++it) {
        const int row = row0 + (it * TY + ty) * RPT;
        const float xa = x[(size_t)row * SN + tx];
        const float xb = x[(size_t)(row + 1) * SN + tx];

        float t1a[H1], d1a[H1], c1a[H1];
        float t1b[H1], d1b[H1], c1b[H1];
        #pragma unroll
        for (int i = 0; i < H1; ++i) {
            const float w  = spx[(0  + i) * 32];
            const float bb = spx[(10 + i) * 32];
            const float ws = spx[(20 + i) * 32];  // -2*w^2
            const float ta = ftanh(fmaf(w, xa, bb));
            const float tb = ftanh(fmaf(w, xb, bb));
            const float sa = fmaf(-ta, ta, 1.0f);
            const float sb = fmaf(-tb, tb, 1.0f);
            t1a[i] = ta;        t1b[i] = tb;
            d1a[i] = sa * w;    d1b[i] = sb * w;
            c1a[i] = ta * sa * ws;
            c1b[i] = tb * sb * ws;
        }

        float oa = spx[102 * 32], ob = oa;
        float ga = 0.0f, gb = 0.0f;
        #pragma unroll
        for (int k = 0; k < H2; ++k) {
            float z2a = spx[(90 + k) * 32], z2b = z2a;
            float ua = 0.f, ub = 0.f, va = 0.f, vb = 0.f;
            #pragma unroll
            for (int i = 0; i < H1; ++i) {
                const float w = spx[(30 + i * 6 + k) * 32];
                z2a = fmaf(w, t1a[i], z2a);  z2b = fmaf(w, t1b[i], z2b);
                ua  = fmaf(w, d1a[i], ua);   ub  = fmaf(w, d1b[i], ub);
                va  = fmaf(w, c1a[i], va);   vb  = fmaf(w, c1b[i], vb);
            }
            const float t2a = ftanh(z2a);
            const float t2b = ftanh(z2b);
            const float s2a = fmaf(-t2a, t2a, 1.0f);
            const float s2b = fmaf(-t2b, t2b, 1.0f);
            const float d2a = s2a * fmaf(-2.0f * t2a, ua * ua, va);
            const float d2b = s2b * fmaf(-2.0f * t2b, ub * ub, vb);
            const float w3 = spx[(96 + k) * 32];
            oa = fmaf(w3, t2a, oa);  ob = fmaf(w3, t2b, ob);
            ga = fmaf(w3, d2a, ga);  gb = fmaf(w3, d2b, gb);
        }

        out[(size_t)row * SN + tx]       = oa;
        out[(size_t)(row + 1) * SN + tx] = ob;
        acc_o  += oa + ob;
        acc_o2 += oa * oa + ob * ob;
        acc_g  += ga * ga + gb * gb;
    }

    // deterministic per-block reduction over ty
    red[0][ty][tx] = acc_o;
    red[1][ty][tx] = acc_o2;
    red[2][ty][tx] = acc_g;
    __syncthreads();
    if (ty < 3) {
        float s = 0.0f;
        #pragma unroll
        for (int j = 0; j < TY; ++j) s += red[ty][j][tx];
        g_partial[blockIdx.x * 96 + ty * 32 + tx] = s;
    }
}

__global__ void k_reduce()
{
    const int b = blockIdx.x;                // 0..95 = stat*32+subnet
    const int t = threadIdx.x;
    double s = 0.0;
    for (int i = t; i < NBLK; i += 256) s += (double)g_partial[i * 96 + b];
    __shared__ double sd[256];
    sd[t] = s;
    __syncthreads();
    for (int o = 128; o > 0; o >>= 1) {
        if (t < o) sd[t] += sd[t + o];
        __syncthreads();
    }
    if (t == 0) g_sums[b] = sd[0];
}

__global__ void k_stats(float* __restrict__ out, int write_loss)
{
    const int s = threadIdx.x;               // subnet
    const double n   = (double)BATCH;
    const double so  = g_sums[0 * 32 + s];
    const double so2 = g_sums[1 * 32 + s];
    const double sg  = g_sums[2 * 32 + s];
    const double mean = so / n;
    const double var  = so2 / n - mean * mean;
    g_mean[s] = (float)mean;
    g_rstd[s] = (float)(1.0 / sqrt(var + 1e-10));
    double pen = (sg / n) / sqrt(var);
    #pragma unroll
    for (int o = 16; o > 0; o >>= 1)
        pen += __shfl_down_sync(0xffffffffu, pen, o);
    if (s == 0 && write_loss)
        out[(size_t)BATCH * SN] = (float)(0.001 * pen);
}

__global__ void __launch_bounds__(256) k_norm(float* __restrict__ out)
{
    __shared__ float sm[32], sr[32];
    if (threadIdx.x < 32) {
        sm[threadIdx.x] = g_mean[threadIdx.x];
        sr[threadIdx.x] = g_rstd[threadIdx.x];
    }
    __syncthreads();
    const size_t idx = ((size_t)blockIdx.x * blockDim.x + threadIdx.x) * 4;
    const int s = (int)(idx & 31);
    float4 v = *reinterpret_cast<float4*>(out + idx);
    v.x = (v.x - sm[s + 0]) * sr[s + 0];
    v.y = (v.y - sm[s + 1]) * sr[s + 1];
    v.z = (v.z - sm[s + 2]) * sr[s + 2];
    v.w = (v.w - sm[s + 3]) * sr[s + 3];
    *reinterpret_cast<float4*>(out + idx) = v;
}

extern "C" void kernel_launch(void* const* d_in, const int* in_sizes, int n_in,
                              void* d_out, int out_size)
{
    const float* x  = (const float*)d_in[0];
    const float* W1 = (const float*)d_in[1];
    const float* b1 = (const float*)d_in[2];
    const float* W2 = (const float*)d_in[3];
    const float* b2 = (const float*)d_in[4];
    const float* W3 = (const float*)d_in[5];
    const float* b3 = (const float*)d_in[6];
    float* out = (float*)d_out;

    dim3 blk(32, TY);
    k_forward<<<NBLK, blk>>>(x, W1, b1, W2, b2, W3, b3, out);
    k_reduce<<<96, 256>>>();
    const int write_loss = (out_size > BATCH * SN) ? 1 : 0;
    k_stats<<<1, 32>>>(out, write_loss);
    k_norm<<<(BATCH * SN / 4) / 256, 256>>>(out);
}